// round 6
// baseline (speedup 1.0000x reference)
#include <cuda_runtime.h>
#include <cuda_bf16.h>
#include <math.h>
#include <stdint.h>

// ---------------------------------------------------------------------------
// RWKV-7 Tmix forward. B=4, T=2048, C=2048, H=32, N=64.
// R6: hgemm CTA tile 128x256 (warp 64x64), prep fused into wkv7/post,
// launch order arranged so ncu (-s 5) profiles a big GEMM.
// ---------------------------------------------------------------------------

#define BB 4
#define TT 2048
#define CC 2048
#define HH 32
#define NN 64
#define BT (BB*TT)                       // 8192
#define BTC ((size_t)BT*(size_t)CC)      // 16777216

__device__ float g_pool[23ull * 16777216ull];

#define SL_XR 0
#define SL_XW 1
#define SL_XK 2
#define SL_XV 3
#define SL_XA 4
#define SL_XG 5
#define SL_R  6
#define SL_K  7
#define SL_VL 8
#define SL_G  9
#define SL_WD 10
#define SL_A  11
#define SL_S  12
#define SL_Y  19
#define SL_ZS 20
#define SL_SMALL 21
#define SL_WB  22

// ===========================================================================
// helpers
// ===========================================================================
__device__ __forceinline__ uint32_t smem_u32(const void* p) {
    uint32_t a;
    asm("{ .reg .u64 t; cvta.to.shared.u64 t, %1; cvt.u32.u64 %0, t; }"
        : "=r"(a) : "l"(p));
    return a;
}
__device__ __forceinline__ void cpasync16(uint32_t dst, const void* src) {
    asm volatile("cp.async.cg.shared.global [%0], [%1], 16;" :: "r"(dst), "l"(src));
}
__device__ __forceinline__ void ldsm4(uint32_t* r, uint32_t addr) {
    asm volatile("ldmatrix.sync.aligned.m8n8.x4.shared.b16 {%0,%1,%2,%3}, [%4];"
        : "=r"(r[0]), "=r"(r[1]), "=r"(r[2]), "=r"(r[3]) : "r"(addr));
}
__device__ __forceinline__ void mma16816(float* d, const uint32_t* a, const uint32_t* b) {
    asm volatile(
        "mma.sync.aligned.m16n8k16.row.col.f32.bf16.bf16.f32 "
        "{%0,%1,%2,%3}, {%4,%5,%6,%7}, {%8,%9}, {%0,%1,%2,%3};"
        : "+f"(d[0]), "+f"(d[1]), "+f"(d[2]), "+f"(d[3])
        : "r"(a[0]), "r"(a[1]), "r"(a[2]), "r"(a[3]), "r"(b[0]), "r"(b[1]));
}
__device__ __forceinline__ uint32_t pack_bf2(float a, float b) {
    __nv_bfloat162 t = __floats2bfloat162_rn(a, b);
    return *reinterpret_cast<uint32_t*>(&t);
}

template<int EPI>
__device__ __forceinline__ float epi_apply(float v, float b) {
    if (EPI == 3) {
        return 1.f / (1.f + expf(-(v + b)));
    } else if (EPI == 4) {
        float z  = v + b;
        float sp = (z < -20.f) ? (-z) : log1pf(expf(-z));
        float w  = -sp - 0.5f;
        return expf(-expf(w));
    }
    return v;
}

// ===========================================================================
// Main tensor GEMM: C[M,Ntot] = (Ah+Al)[M,K(lda)] @ (Bh+Bl)[Ntot,K]^T
// D = Ah*Bh + Ah*Bl + Al*Bh, fp32 accum. CTA tile 128x256x32 (warp 64x64),
// 3-stage cp.async pipeline.
// ===========================================================================
#define PADK 40
#define A_TILE (128*PADK*2)              // 10240
#define B_TILE (256*PADK*2)              // 20480
#define STG_B  (2*A_TILE + 2*B_TILE)     // 61440
#define HSTAGES 3
#define HSMEM  (HSTAGES*STG_B)           // 184320

template<int EPI>
__global__ void __launch_bounds__(256, 1)
hgemm(const __nv_bfloat16* __restrict__ Ah, const __nv_bfloat16* __restrict__ Al,
      const __nv_bfloat16* __restrict__ Bh, const __nv_bfloat16* __restrict__ Bl,
      float* __restrict__ C, int K, int lda, int Ntot, const float* __restrict__ bias)
{
    extern __shared__ char sm[];
    const int tid  = threadIdx.x;
    const int lane = tid & 31;
    const int wid  = tid >> 5;
    const int m0 = blockIdx.y * 128;
    const int n0 = blockIdx.x * 256;
    const int mw = (wid >> 2) * 64;      // 2 warps in m
    const int nw = (wid & 3) * 64;       // 4 warps in n
    const uint32_t sbase = smem_u32(sm);
    const int KT = K >> 5;

    float acc[4][8][4];
#pragma unroll
    for (int mt = 0; mt < 4; mt++)
#pragma unroll
        for (int nt = 0; nt < 8; nt++)
#pragma unroll
            for (int q = 0; q < 4; q++) acc[mt][nt][q] = 0.f;

    auto issue = [&](int kt, int stage) {
        const int k0 = kt << 5;
        const uint32_t sdst = sbase + stage * STG_B;
#pragma unroll
        for (int u = 0; u < 12; u++) {
            int i = tid + u * 256;
            if (i < 1024) {          // A: 128 rows x 4 chunks x 2 splits
                int sp = i >> 9, r = (i >> 2) & 127, c = i & 3;
                const __nv_bfloat16* src = (sp ? Al : Ah) + (size_t)(m0 + r) * lda + k0 + c * 8;
                cpasync16(sdst + sp * A_TILE + r * (PADK*2) + c * 16, src);
            } else {                 // B: 256 rows x 4 chunks x 2 splits
                int j = i - 1024;
                int sp = j >> 10, r = (j >> 2) & 255, c = j & 3;
                const __nv_bfloat16* src = (sp ? Bl : Bh) + (size_t)(n0 + r) * K + k0 + c * 8;
                cpasync16(sdst + 2*A_TILE + sp * B_TILE + r * (PADK*2) + c * 16, src);
            }
        }
    };

#pragma unroll
    for (int s = 0; s < HSTAGES - 1; s++) {
        if (s < KT) issue(s, s);
        asm volatile("cp.async.commit_group;" ::: "memory");
    }

    const int grp = lane >> 3;
    const int l7  = lane & 7;

    for (int kt = 0; kt < KT; kt++) {
        asm volatile("cp.async.wait_group 1;" ::: "memory");
        __syncthreads();

        const int st = kt % HSTAGES;
        const uint32_t sAh = sbase + st * STG_B;
        const uint32_t sAl = sAh + A_TILE;
        const uint32_t sBh = sAh + 2 * A_TILE;
        const uint32_t sBl = sBh + B_TILE;

#pragma unroll
        for (int kk = 0; kk < 2; kk++) {
            const int ko = kk * 16;
            uint32_t ahf[4][4], alf[4][4], bhf[8][2], blf[8][2];
#pragma unroll
            for (int mt = 0; mt < 4; mt++) {
                int row = mw + mt * 16 + ((grp & 1) << 3) + l7;
                int kof = ko + ((grp & 2) << 2);
                uint32_t a = row * (PADK*2) + kof * 2;
                ldsm4(ahf[mt], sAh + a);
                ldsm4(alf[mt], sAl + a);
            }
#pragma unroll
            for (int np = 0; np < 4; np++) {
                int row = nw + np * 16 + ((grp >> 1) << 3) + l7;
                int kof = ko + ((grp & 1) << 3);
                uint32_t a = row * (PADK*2) + kof * 2;
                uint32_t t[4];
                ldsm4(t, sBh + a);
                bhf[np*2][0]   = t[0]; bhf[np*2][1]   = t[1];
                bhf[np*2+1][0] = t[2]; bhf[np*2+1][1] = t[3];
                ldsm4(t, sBl + a);
                blf[np*2][0]   = t[0]; blf[np*2][1]   = t[1];
                blf[np*2+1][0] = t[2]; blf[np*2+1][1] = t[3];
            }
#pragma unroll
            for (int mt = 0; mt < 4; mt++)
#pragma unroll
                for (int nt = 0; nt < 8; nt++) {
                    mma16816(acc[mt][nt], ahf[mt], bhf[nt]);
                    mma16816(acc[mt][nt], ahf[mt], blf[nt]);
                    mma16816(acc[mt][nt], alf[mt], bhf[nt]);
                }
        }

        int nkt = kt + HSTAGES - 1;
        if (nkt < KT) issue(nkt, nkt % HSTAGES);
        asm volatile("cp.async.commit_group;" ::: "memory");
    }

    const int r0 = lane >> 2;
    const int c0 = (lane & 3) * 2;
#pragma unroll
    for (int mt = 0; mt < 4; mt++) {
#pragma unroll
        for (int nt = 0; nt < 8; nt++) {
            int row = m0 + mw + mt * 16 + r0;
            int col = n0 + nw + nt * 8 + c0;
            float b0 = 0.f, b1 = 0.f;
            if (EPI != 0) { b0 = bias[col]; b1 = bias[col + 1]; }
            float v0 = epi_apply<EPI>(acc[mt][nt][0], b0);
            float v1 = epi_apply<EPI>(acc[mt][nt][1], b1);
            float v2 = epi_apply<EPI>(acc[mt][nt][2], b0);
            float v3 = epi_apply<EPI>(acc[mt][nt][3], b1);
            *(float2*)(C + (size_t)row * Ntot + col)       = make_float2(v0, v1);
            *(float2*)(C + (size_t)(row + 8) * Ntot + col) = make_float2(v2, v3);
        }
    }
}

// ===========================================================================
// Stage-1 fused LoRA GEMM (unchanged from R5): 5 column segments.
// ===========================================================================
#define S1_ATILE (128*PADK*2)
#define S1_BTILE (64*PADK*2)
#define S1_STG   (2*S1_ATILE + 2*S1_BTILE)
#define S1_SMEM  (3*S1_STG)
#define HCATN 320

__global__ void __launch_bounds__(256, 1)
hgemm_s1(const __nv_bfloat16* __restrict__ xw_h, const __nv_bfloat16* __restrict__ xw_l,
         const __nv_bfloat16* __restrict__ xa_h, const __nv_bfloat16* __restrict__ xa_l,
         const __nv_bfloat16* __restrict__ xg_h, const __nv_bfloat16* __restrict__ xg_l,
         const __nv_bfloat16* __restrict__ xv_h, const __nv_bfloat16* __restrict__ xv_l,
         const __nv_bfloat16* __restrict__ W1h, const __nv_bfloat16* __restrict__ W1l,
         __nv_bfloat16* __restrict__ Hh, __nv_bfloat16* __restrict__ Hl)
{
    extern __shared__ char sm[];
    const int tid  = threadIdx.x;
    const int lane = tid & 31;
    const int wid  = tid >> 5;
    const int seg  = blockIdx.x;
    const int m0   = blockIdx.y * 128;
    const int n0w  = seg * 64;
    const uint32_t sbase = smem_u32(sm);

    const __nv_bfloat16* Ah;
    const __nv_bfloat16* Al;
    if (seg == 0)      { Ah = xw_h; Al = xw_l; }
    else if (seg == 1) { Ah = xa_h; Al = xa_l; }
    else if (seg <= 3) { Ah = xg_h; Al = xg_l; }
    else               { Ah = xv_h; Al = xv_l; }

    const int mw = (wid >> 1) * 32;
    const int nw = (wid & 1) * 32;

    float acc[2][4][4];
#pragma unroll
    for (int mt = 0; mt < 2; mt++)
#pragma unroll
        for (int nt = 0; nt < 4; nt++)
#pragma unroll
            for (int q = 0; q < 4; q++) acc[mt][nt][q] = 0.f;

    auto issue = [&](int kt, int stage) {
        const int k0 = kt << 5;
        const uint32_t sdst = sbase + stage * S1_STG;
#pragma unroll
        for (int u = 0; u < 6; u++) {
            int i = tid + u * 256;
            if (i < 1024) {
                int sp = i >> 9, r = (i >> 2) & 127, c = i & 3;
                const __nv_bfloat16* src = (sp ? Al : Ah) + (size_t)(m0 + r) * CC + k0 + c * 8;
                cpasync16(sdst + sp * S1_ATILE + r * (PADK*2) + c * 16, src);
            } else {
                int j = i - 1024;
                int sp = j >> 8, r = (j >> 2) & 63, c = j & 3;
                const __nv_bfloat16* src = (sp ? W1l : W1h) + (size_t)(n0w + r) * CC + k0 + c * 8;
                cpasync16(sdst + 2*S1_ATILE + sp * S1_BTILE + r * (PADK*2) + c * 16, src);
            }
        }
    };

#pragma unroll
    for (int s = 0; s < 2; s++) {
        issue(s, s);
        asm volatile("cp.async.commit_group;" ::: "memory");
    }

    const int grp = lane >> 3;
    const int l7  = lane & 7;
    const int KT = CC >> 5;

    for (int kt = 0; kt < KT; kt++) {
        asm volatile("cp.async.wait_group 1;" ::: "memory");
        __syncthreads();

        const int st = kt % 3;
        const uint32_t sAh = sbase + st * S1_STG;
        const uint32_t sAl = sAh + S1_ATILE;
        const uint32_t sBh = sAh + 2 * S1_ATILE;
        const uint32_t sBl = sBh + S1_BTILE;

#pragma unroll
        for (int kk = 0; kk < 2; kk++) {
            const int ko = kk * 16;
            uint32_t ahf[2][4], alf[2][4], bhf[4][2], blf[4][2];
#pragma unroll
            for (int mt = 0; mt < 2; mt++) {
                int row = mw + mt * 16 + ((grp & 1) << 3) + l7;
                int kof = ko + ((grp & 2) << 2);
                uint32_t a = row * (PADK*2) + kof * 2;
                ldsm4(ahf[mt], sAh + a);
                ldsm4(alf[mt], sAl + a);
            }
#pragma unroll
            for (int np = 0; np < 2; np++) {
                int row = nw + np * 16 + ((grp >> 1) << 3) + l7;
                int kof = ko + ((grp & 1) << 3);
                uint32_t a = row * (PADK*2) + kof * 2;
                uint32_t t[4];
                ldsm4(t, sBh + a);
                bhf[np*2][0]   = t[0]; bhf[np*2][1]   = t[1];
                bhf[np*2+1][0] = t[2]; bhf[np*2+1][1] = t[3];
                ldsm4(t, sBl + a);
                blf[np*2][0]   = t[0]; blf[np*2][1]   = t[1];
                blf[np*2+1][0] = t[2]; blf[np*2+1][1] = t[3];
            }
#pragma unroll
            for (int mt = 0; mt < 2; mt++)
#pragma unroll
                for (int nt = 0; nt < 4; nt++) {
                    mma16816(acc[mt][nt], ahf[mt], bhf[nt]);
                    mma16816(acc[mt][nt], ahf[mt], blf[nt]);
                    mma16816(acc[mt][nt], alf[mt], bhf[nt]);
                }
        }

        int nkt = kt + 2;
        if (nkt < KT) issue(nkt, nkt % 3);
        asm volatile("cp.async.commit_group;" ::: "memory");
    }

    const int r0 = lane >> 2;
    const int c0 = (lane & 3) * 2;
#pragma unroll
    for (int mt = 0; mt < 2; mt++) {
#pragma unroll
        for (int nt = 0; nt < 4; nt++) {
            float v[4];
#pragma unroll
            for (int q = 0; q < 4; q++) {
                float t = acc[mt][nt][q];
                if (seg == 0)              t = tanhf(t);
                else if (seg == 2 || seg == 3) t = 1.f / (1.f + expf(-t));
                v[q] = t;
            }
            int row = m0 + mw + mt * 16 + r0;
            int col = seg * 64 + nw + nt * 8 + c0;
            float h0 = __bfloat162float(__float2bfloat16(v[0]));
            float h1 = __bfloat162float(__float2bfloat16(v[1]));
            float h2 = __bfloat162float(__float2bfloat16(v[2]));
            float h3 = __bfloat162float(__float2bfloat16(v[3]));
            *(uint32_t*)&Hh[(size_t)row * HCATN + col]       = pack_bf2(v[0], v[1]);
            *(uint32_t*)&Hl[(size_t)row * HCATN + col]       = pack_bf2(v[0]-h0, v[1]-h1);
            *(uint32_t*)&Hh[(size_t)(row+8) * HCATN + col]   = pack_bf2(v[2], v[3]);
            *(uint32_t*)&Hl[(size_t)(row+8) * HCATN + col]   = pack_bf2(v[2]-h2, v[3]-h3);
        }
    }
}

// ===========================================================================
// Weight transpose + split: W[K][N] fp32 -> Th/Tl[N][K] bf16
// ===========================================================================
__global__ void transpose_split(const float* __restrict__ W,
                                __nv_bfloat16* __restrict__ Th,
                                __nv_bfloat16* __restrict__ Tl, int K, int N)
{
    __shared__ float tile[32][33];
    int bx = blockIdx.x * 32;
    int by = blockIdx.y * 32;
#pragma unroll
    for (int j = 0; j < 32; j += 8)
        tile[threadIdx.y + j][threadIdx.x] =
            W[(size_t)(by + threadIdx.y + j) * N + bx + threadIdx.x];
    __syncthreads();
#pragma unroll
    for (int j = 0; j < 32; j += 8) {
        float v = tile[threadIdx.x][threadIdx.y + j];
        int n = bx + threadIdx.y + j;
        int k = by + threadIdx.x;
        __nv_bfloat16 h = __float2bfloat16(v);
        Th[(size_t)n * K + k] = h;
        Tl[(size_t)n * K + k] = __float2bfloat16(v - __bfloat162float(h));
    }
}

// ---------------------------------------------------------------------------
// Token-shift mixing, fused bf16 hi/lo split output for all 6 streams.
// ---------------------------------------------------------------------------
__global__ void mix_split_kernel(const float* __restrict__ x,
    const float* __restrict__ mr, const float* __restrict__ mw,
    const float* __restrict__ mk, const float* __restrict__ mv,
    const float* __restrict__ ma, const float* __restrict__ mg,
    __nv_bfloat16* __restrict__ rh, __nv_bfloat16* __restrict__ rl,
    __nv_bfloat16* __restrict__ wh, __nv_bfloat16* __restrict__ wl,
    __nv_bfloat16* __restrict__ kh, __nv_bfloat16* __restrict__ kl,
    __nv_bfloat16* __restrict__ vh, __nv_bfloat16* __restrict__ vl,
    __nv_bfloat16* __restrict__ ah, __nv_bfloat16* __restrict__ al,
    __nv_bfloat16* __restrict__ gh, __nv_bfloat16* __restrict__ gl)
{
    size_t i = (size_t)blockIdx.x * blockDim.x + threadIdx.x;
    size_t n4 = BTC / 4;
    if (i >= n4) return;
    size_t e = i * 4;
    int c  = (int)(e % CC);
    int bt = (int)(e / CC);
    int t  = bt % TT;

    float4 xc = ((const float4*)x)[i];
    float4 xp = make_float4(0.f, 0.f, 0.f, 0.f);
    if (t > 0) xp = ((const float4*)x)[i - CC/4];
    float4 xx = make_float4(xp.x-xc.x, xp.y-xc.y, xp.z-xc.z, xp.w-xc.w);

    int c4 = c / 4;
#define DOMIX(MV, OH, OL) { \
        float4 m = ((const float4*)MV)[c4]; \
        float4 o = make_float4(xc.x + xx.x*m.x, xc.y + xx.y*m.y, \
                               xc.z + xx.z*m.z, xc.w + xx.w*m.w); \
        float h0 = __bfloat162float(__float2bfloat16(o.x)); \
        float h1 = __bfloat162float(__float2bfloat16(o.y)); \
        float h2 = __bfloat162float(__float2bfloat16(o.z)); \
        float h3 = __bfloat162float(__float2bfloat16(o.w)); \
        ((uint2*)OH)[i] = make_uint2(pack_bf2(o.x, o.y), pack_bf2(o.z, o.w)); \
        ((uint2*)OL)[i] = make_uint2(pack_bf2(o.x-h0, o.y-h1), pack_bf2(o.z-h2, o.w-h3)); }
    DOMIX(mr, rh, rl); DOMIX(mw, wh, wl); DOMIX(mk, kh, kl);
    DOMIX(mv, vh, vl); DOMIX(ma, ah, al); DOMIX(mg, gh, gl);
#undef DOMIX
}

// ---------------------------------------------------------------------------
__device__ __forceinline__ float warp_sum(float v) {
#pragma unroll
    for (int o = 16; o > 0; o >>= 1) v += __shfl_xor_sync(0xffffffffu, v, o);
    return v;
}

// ---------------------------------------------------------------------------
// WKV7 recurrence with fused prep. 256 threads/block, one block per (b,h).
// Staging groups (tid>>6): 0=r, 1=wd, 2={k,a}->fk,aa_un,bb_un,ssq, 3={vl,s,v0}->fv.
// Consumers: thread (row=tid>>2, cg=tid&3) owns S[row][cg*16..+15].
// Norm folded in: sai = (S . aa_un) * inv^2, term sai*bb_un == true sa.b.
// ---------------------------------------------------------------------------
__global__ void __launch_bounds__(256)
wkv7_kernel(const float* __restrict__ r_,  const float* __restrict__ wd_,
            const float* __restrict__ k_,  const float* __restrict__ a_,
            const float* __restrict__ vl_, const float* __restrict__ s_,
            const float* __restrict__ v0_,
            const float* __restrict__ misc_kkk, const float* __restrict__ misc_a,
            float* __restrict__ yT)
{
    __shared__ __align__(16) float sb[2*392];   // 6*64 staged + pad + 2 ssq partials
    const int bh  = blockIdx.x;
    const int b   = bh >> 5, h = bh & 31;
    const int tid = threadIdx.x;
    const int tg  = tid >> 6;
    const int n   = tid & 63;
    const int row = tid >> 2;
    const int cg  = tid & 3;
    const int cb  = cg * 16;
    const size_t src0  = ((size_t)b * TT) * CC + (size_t)h * NN + n;
    const size_t ybase = (size_t)bh * TT * NN;

    const float* pA;
    const float* pB = nullptr;
    const float* pC = nullptr;
    float ma = 0.f, mkk = 0.f;
    if (tg == 0)      pA = r_  + src0;
    else if (tg == 1) pA = wd_ + src0;
    else if (tg == 2) { pA = k_ + src0; pB = a_ + src0;
                        mkk = misc_kkk[h*NN+n]; ma = misc_a[h*NN+n]; }
    else              { pA = vl_ + src0; pB = s_ + src0; pC = v0_ + src0; }

    float st[16];
#pragma unroll
    for (int j = 0; j < 16; j++) st[j] = 0.f;

    // initial staging (t=0) into buffer 0
    {
        float va = pA[0];
        if (tg == 0)      sb[0*64+n] = va;
        else if (tg == 1) sb[1*64+n] = va;
        else if (tg == 2) {
            float vb = pB[0];
            float kk = va * mkk;
            sb[2*64+n] = va * fmaf(vb - 1.f, ma, 1.f);
            sb[4*64+n] = -kk;
            sb[5*64+n] = kk * vb;
            float wsum = warp_sum(kk*kk);
            if ((tid & 31) == 0) sb[384 + ((tid >> 5) & 1)] = wsum;
        } else {
            float vb = pB[0], vc = pC[0];
            sb[3*64+n] = va + (vc - va) * vb;
        }
    }
    __syncthreads();

    int cur = 0;
    for (int t = 0; t < TT; t++) {
        float fa = 0.f, fb = 0.f, fc = 0.f;
        if (t + 1 < TT) {
            size_t o = (size_t)(t + 1) * CC;
            fa = pA[o];
            if (tg >= 2) fb = pB[o];
            if (tg == 3) fc = pC[o];
        }

        const float* base = &sb[cur * 392];
        float ssq  = base[384] + base[385];
        float invn = 1.f / fmaxf(sqrtf(ssq), 1e-12f);
        float f2   = invn * invn;

        const float4* r4p = (const float4*)(base + 0*64 + cb);
        const float4* w4p = (const float4*)(base + 1*64 + cb);
        const float4* k4p = (const float4*)(base + 2*64 + cb);
        const float4* a4p = (const float4*)(base + 4*64 + cb);
        const float4* b4p = (const float4*)(base + 5*64 + cb);
        const float vi = base[3*64 + row];

        float c0=0.f, c1=0.f, c2=0.f, c3=0.f;
#pragma unroll
        for (int q = 0; q < 4; q++) {
            float4 a4 = a4p[q];
            c0 = fmaf(st[q*4+0], a4.x, c0);
            c1 = fmaf(st[q*4+1], a4.y, c1);
            c2 = fmaf(st[q*4+2], a4.z, c2);
            c3 = fmaf(st[q*4+3], a4.w, c3);
        }
        float sai = (c0 + c1) + (c2 + c3);
        sai += __shfl_xor_sync(0xffffffffu, sai, 1);
        sai += __shfl_xor_sync(0xffffffffu, sai, 2);
        sai *= f2;     // fold 1/||kk||^2 (covers aa and bb normalization)

        float y0=0.f, y1=0.f, y2=0.f, y3=0.f;
#pragma unroll
        for (int q = 0; q < 4; q++) {
            float4 w4 = w4p[q], b4 = b4p[q], k4 = k4p[q], r4 = r4p[q];
            float t0 = fmaf(sai, b4.x, fmaf(vi, k4.x, st[q*4+0]*w4.x));
            float t1 = fmaf(sai, b4.y, fmaf(vi, k4.y, st[q*4+1]*w4.y));
            float t2 = fmaf(sai, b4.z, fmaf(vi, k4.z, st[q*4+2]*w4.z));
            float t3 = fmaf(sai, b4.w, fmaf(vi, k4.w, st[q*4+3]*w4.w));
            st[q*4+0] = t0; st[q*4+1] = t1; st[q*4+2] = t2; st[q*4+3] = t3;
            y0 = fmaf(t0, r4.x, y0);
            y1 = fmaf(t1, r4.y, y1);
            y2 = fmaf(t2, r4.z, y2);
            y3 = fmaf(t3, r4.w, y3);
        }
        float yp = (y0 + y1) + (y2 + y3);
        yp += __shfl_xor_sync(0xffffffffu, yp, 1);
        yp += __shfl_xor_sync(0xffffffffu, yp, 2);
        if (cg == 0) yT[ybase + (size_t)t * NN + row] = yp;

        int nxt = cur ^ 1;
        if (t + 1 < TT) {
            float* d = &sb[nxt * 392];
            if (tg == 0)      d[0*64+n] = fa;
            else if (tg == 1) d[1*64+n] = fa;
            else if (tg == 2) {
                float kk = fa * mkk;
                d[2*64+n] = fa * fmaf(fb - 1.f, ma, 1.f);
                d[4*64+n] = -kk;
                d[5*64+n] = kk * fb;
                float wsum = warp_sum(kk*kk);
                if ((tid & 31) == 0) d[384 + ((tid >> 5) & 1)] = wsum;
            } else {
                d[3*64+n] = fa + (fc - fa) * fb;
            }
        }
        __syncthreads();
        cur = nxt;
    }
}

// ---------------------------------------------------------------------------
// GroupNorm + bonus + gate (prep transforms recomputed inline).
// ---------------------------------------------------------------------------
__global__ void post_kernel(const float* __restrict__ yT,
                            const float* __restrict__ r_, const float* __restrict__ k_,
                            const float* __restrict__ a_, const float* __restrict__ vl_,
                            const float* __restrict__ s_, const float* __restrict__ v0_,
                            const float* __restrict__ g,  const float* __restrict__ faaaa,
                            const float* __restrict__ misc_a,
                            const float* __restrict__ lnw, const float* __restrict__ lnb,
                            __nv_bfloat16* __restrict__ zh, __nv_bfloat16* __restrict__ zl)
{
    int gw   = (blockIdx.x * blockDim.x + threadIdx.x) >> 5;
    int lane = threadIdx.x & 31;
    if (gw >= BT * HH) return;
    int h  = gw % HH;
    int bt = gw / HH;
    int b  = bt / TT, t = bt % TT;

    size_t src = (size_t)bt * CC + (size_t)h * NN;
    size_t dst = (((size_t)(b*HH + h)) * TT + t) * NN;
    int n0 = lane, n1 = lane + 32;
    int c0 = h*NN + n0, c1 = h*NN + n1;

    float y0 = yT[dst+n0], y1 = yT[dst+n1];
    float sum = warp_sum(y0 + y1);
    float sq  = warp_sum(y0*y0 + y1*y1);
    float mu  = sum * (1.f/64.f);
    float var = sq * (1.f/64.f) - mu*mu;
    float rs  = rsqrtf(var + 6.4e-4f);

    float k0 = k_[src+n0], k1 = k_[src+n1];
    float a0 = a_[src+n0], a1 = a_[src+n1];
    float fk0 = k0 * fmaf(a0 - 1.f, misc_a[c0], 1.f);
    float fk1 = k1 * fmaf(a1 - 1.f, misc_a[c1], 1.f);
    float rk = r_[src+n0]*fk0*faaaa[c0] + r_[src+n1]*fk1*faaaa[c1];
    float srk = warp_sum(rk);

    float vv0 = vl_[src+n0], vv1 = vl_[src+n1];
    float fv0 = vv0 + (v0_[src+n0] - vv0) * s_[src+n0];
    float fv1 = vv1 + (v0_[src+n1] - vv1) * s_[src+n1];

    float z0 = ((y0 - mu)*rs*lnw[c0] + lnb[c0] + srk*fv0) * g[src+n0];
    float z1 = ((y1 - mu)*rs*lnw[c1] + lnb[c1] + srk*fv1) * g[src+n1];
    __nv_bfloat16 h0 = __float2bfloat16(z0);
    __nv_bfloat16 h1 = __float2bfloat16(z1);
    zh[src+n0] = h0; zh[src+n1] = h1;
    zl[src+n0] = __float2bfloat16(z0 - __bfloat162float(h0));
    zl[src+n1] = __float2bfloat16(z1 - __bfloat162float(h1));
}

__global__ void copy4_kernel(const float* __restrict__ src, float* __restrict__ dst,
                             size_t n4)
{
    size_t i = (size_t)blockIdx.x * blockDim.x + threadIdx.x;
    if (i < n4) ((float4*)dst)[i] = ((const float4*)src)[i];
}

// ---------------------------------------------------------------------------
// launch
// ---------------------------------------------------------------------------
extern "C" void kernel_launch(void* const* d_in, const int* in_sizes, int n_in,
                              void* d_out, int out_size)
{
    const float* x         = (const float*)d_in[0];
    const float* v0        = (const float*)d_in[1];
    const float* maa_r     = (const float*)d_in[2];
    const float* maa_w     = (const float*)d_in[3];
    const float* maa_k     = (const float*)d_in[4];
    const float* maa_v     = (const float*)d_in[5];
    const float* maa_a     = (const float*)d_in[6];
    const float* maa_g     = (const float*)d_in[7];
    const float* time_decay= (const float*)d_in[8];
    const float* faaaa     = (const float*)d_in[9];
    const float* time_aaaaa= (const float*)d_in[10];
    const float* td_w1     = (const float*)d_in[11];
    const float* td_w2     = (const float*)d_in[12];
    const float* aaa_w1    = (const float*)d_in[13];
    const float* aaa_w2    = (const float*)d_in[14];
    const float* gate_w1   = (const float*)d_in[15];
    const float* gate_w2   = (const float*)d_in[16];
    const float* mv_w1     = (const float*)d_in[17];
    const float* mv_w2     = (const float*)d_in[18];
    const float* misc_v    = (const float*)d_in[19];
    const float* misc_kkk  = (const float*)d_in[20];
    const float* misc_a    = (const float*)d_in[21];
    const float* Wr        = (const float*)d_in[22];
    const float* Wk        = (const float*)d_in[23];
    const float* Wv        = (const float*)d_in[24];
    const float* Wo        = (const float*)d_in[25];
    const float* ln_w      = (const float*)d_in[26];
    const float* ln_b      = (const float*)d_in[27];

    float* pool = nullptr;
    cudaGetSymbolAddress((void**)&pool, g_pool);

    __nv_bfloat16* xr_h = (__nv_bfloat16*)(pool + (size_t)SL_XR * BTC);
    __nv_bfloat16* xr_l = xr_h + BTC;
    __nv_bfloat16* xw_h = (__nv_bfloat16*)(pool + (size_t)SL_XW * BTC);
    __nv_bfloat16* xw_l = xw_h + BTC;
    __nv_bfloat16* xk_h = (__nv_bfloat16*)(pool + (size_t)SL_XK * BTC);
    __nv_bfloat16* xk_l = xk_h + BTC;
    __nv_bfloat16* xv_h = (__nv_bfloat16*)(pool + (size_t)SL_XV * BTC);
    __nv_bfloat16* xv_l = xv_h + BTC;
    __nv_bfloat16* xa_h = (__nv_bfloat16*)(pool + (size_t)SL_XA * BTC);
    __nv_bfloat16* xa_l = xa_h + BTC;
    __nv_bfloat16* xg_h = (__nv_bfloat16*)(pool + (size_t)SL_XG * BTC);
    __nv_bfloat16* xg_l = xg_h + BTC;

    float* r_ = pool + (size_t)SL_R  * BTC;
    float* k_ = pool + (size_t)SL_K  * BTC;
    float* vl = pool + (size_t)SL_VL * BTC;
    float* g_ = pool + (size_t)SL_G  * BTC;
    float* wd = pool + (size_t)SL_WD * BTC;
    float* a_ = pool + (size_t)SL_A  * BTC;
    float* s_ = pool + (size_t)SL_S  * BTC;
    float* yT = pool + (size_t)SL_Y  * BTC;
    __nv_bfloat16* z_h = (__nv_bfloat16*)(pool + (size_t)SL_ZS * BTC);
    __nv_bfloat16* z_l = z_h + BTC;

    __nv_bfloat16* sb16 = (__nv_bfloat16*)(pool + (size_t)SL_SMALL * BTC);
    __nv_bfloat16* hcat_h = sb16;
    __nv_bfloat16* hcat_l = hcat_h + (size_t)BT * HCATN;
    __nv_bfloat16* W1h    = hcat_l + (size_t)BT * HCATN;
    __nv_bfloat16* W1l    = W1h + (size_t)HCATN * CC;
    __nv_bfloat16* tdw_h  = W1l + (size_t)HCATN * CC;
    __nv_bfloat16* tdw_l  = tdw_h  + (size_t)CC * 64;
    __nv_bfloat16* aaaw_h = tdw_l  + (size_t)CC * 64;
    __nv_bfloat16* aaaw_l = aaaw_h + (size_t)CC * 64;
    __nv_bfloat16* gatew_h= aaaw_l + (size_t)CC * 64;
    __nv_bfloat16* gatew_l= gatew_h+ (size_t)CC * 128;
    __nv_bfloat16* mvw_h  = gatew_l+ (size_t)CC * 128;
    __nv_bfloat16* mvw_l  = mvw_h  + (size_t)CC * 32;

    __nv_bfloat16* wb = (__nv_bfloat16*)(pool + (size_t)SL_WB * BTC);
    const size_t WSZ = (size_t)CC * CC;
    __nv_bfloat16* Wr_h = wb;            __nv_bfloat16* Wr_l = wb + WSZ;
    __nv_bfloat16* Wk_h = wb + 2*WSZ;    __nv_bfloat16* Wk_l = wb + 3*WSZ;
    __nv_bfloat16* Wv_h = wb + 4*WSZ;    __nv_bfloat16* Wv_l = wb + 5*WSZ;
    __nv_bfloat16* Wo_h = wb + 6*WSZ;    __nv_bfloat16* Wo_l = wb + 7*WSZ;

    cudaFuncSetAttribute(hgemm<0>, cudaFuncAttributeMaxDynamicSharedMemorySize, HSMEM);
    cudaFuncSetAttribute(hgemm<3>, cudaFuncAttributeMaxDynamicSharedMemorySize, HSMEM);
    cudaFuncSetAttribute(hgemm<4>, cudaFuncAttributeMaxDynamicSharedMemorySize, HSMEM);
    cudaFuncSetAttribute(hgemm_s1, cudaFuncAttributeMaxDynamicSharedMemorySize, S1_SMEM);

    dim3 tb(32, 8);
    dim3 gBig(CC/256, BT/128);          // (8, 64)
    size_t n4 = BTC / 4;

    // launches 0-2: big weight transposes for r/k/v
    transpose_split<<<dim3(CC/32, CC/32), tb>>>(Wr, Wr_h, Wr_l, CC, CC);
    transpose_split<<<dim3(CC/32, CC/32), tb>>>(Wk, Wk_h, Wk_l, CC, CC);
    transpose_split<<<dim3(CC/32, CC/32), tb>>>(Wv, Wv_h, Wv_l, CC, CC);
    // launch 3: mixing
    mix_split_kernel<<<(unsigned)((n4 + 255) / 256), 256>>>(
        x, maa_r, maa_w, maa_k, maa_v, maa_a, maa_g,
        xr_h, xr_l, xw_h, xw_l, xk_h, xk_l, xv_h, xv_l, xa_h, xa_l, xg_h, xg_l);
    // launches 4-6: big projections (launch 5 = hgemm k, profiled by ncu -s 5)
    hgemm<0><<<gBig, 256, HSMEM>>>(xr_h, xr_l, Wr_h, Wr_l, r_, CC, CC, CC, nullptr);
    hgemm<0><<<gBig, 256, HSMEM>>>(xk_h, xk_l, Wk_h, Wk_l, k_, CC, CC, CC, nullptr);
    hgemm<0><<<gBig, 256, HSMEM>>>(xv_h, xv_l, Wv_h, Wv_l, vl, CC, CC, CC, nullptr);

    // remaining transposes
    transpose_split<<<dim3(CC/32, CC/32), tb>>>(Wo, Wo_h, Wo_l, CC, CC);
    transpose_split<<<dim3(64/32,  CC/32), tb>>>(td_w1,   W1h,                 W1l,                 CC, 64);
    transpose_split<<<dim3(64/32,  CC/32), tb>>>(aaa_w1,  W1h + (size_t)64*CC, W1l + (size_t)64*CC, CC, 64);
    transpose_split<<<dim3(128/32, CC/32), tb>>>(gate_w1, W1h + (size_t)128*CC,W1l + (size_t)128*CC,CC, 128);
    transpose_split<<<dim3(32/32,  CC/32), tb>>>(mv_w1,   W1h + (size_t)256*CC,W1l + (size_t)256*CC,CC, 32);
    transpose_split<<<dim3(CC/32, 64/32),  tb>>>(td_w2,  tdw_h,  tdw_l,  64,  CC);
    transpose_split<<<dim3(CC/32, 64/32),  tb>>>(aaa_w2, aaaw_h, aaaw_l, 64,  CC);
    transpose_split<<<dim3(CC/32, 128/32), tb>>>(gate_w2,gatew_h,gatew_l,128, CC);
    transpose_split<<<dim3(CC/32, 32/32),  tb>>>(mv_w2,  mvw_h,  mvw_l,  32,  CC);

    // stage-1 fused LoRA GEMM
    hgemm_s1<<<dim3(5, BT/128), 256, S1_SMEM>>>(
        xw_h, xw_l, xa_h, xa_l, xg_h, xg_l, xv_h, xv_l, W1h, W1l, hcat_h, hcat_l);

    // stage-2 GEMMs (fused epilogues)
    hgemm<4><<<gBig, 256, HSMEM>>>(hcat_h,     hcat_l,     tdw_h,  tdw_l,  wd, 64,  HCATN, CC, time_decay);
    hgemm<3><<<gBig, 256, HSMEM>>>(hcat_h+64,  hcat_l+64,  aaaw_h, aaaw_l, a_, 64,  HCATN, CC, time_aaaaa);
    hgemm<0><<<gBig, 256, HSMEM>>>(hcat_h+128, hcat_l+128, gatew_h,gatew_l,g_, 128, HCATN, CC, nullptr);
    hgemm<3><<<gBig, 256, HSMEM>>>(hcat_h+256, hcat_l+256, mvw_h,  mvw_l,  s_, 32,  HCATN, CC, misc_v);

    // WKV7 recurrence (prep fused into staging)
    wkv7_kernel<<<BB*HH, 256>>>(r_, wd, k_, a_, vl, s_, v0, misc_kkk, misc_a, yT);

    // groupnorm + bonus + gate -> z split
    post_kernel<<<(BT*HH)/8, 256>>>(yT, r_, k_, a_, vl, s_, v0, g_, faaaa,
                                    misc_a, ln_w, ln_b, z_h, z_l);

    // output projection directly into d_out
    hgemm<0><<<gBig, 256, HSMEM>>>(z_h, z_l, Wo_h, Wo_l, (float*)d_out, CC, CC, CC, nullptr);

    // second output: v0 passthrough
    if ((size_t)out_size >= 2 * BTC) {
        copy4_kernel<<<(unsigned)((n4 + 255) / 256), 256>>>(
            v0, (float*)d_out + BTC, n4);
    }
}

// round 7
// speedup vs baseline: 1.0575x; 1.0575x over previous
#include <cuda_runtime.h>
#include <cuda_bf16.h>
#include <math.h>
#include <stdint.h>

// ---------------------------------------------------------------------------
// RWKV-7 Tmix forward. B=4, T=2048, C=2048, H=32, N=64.
// R7: R5's proven hgemm (128x128x32, 4-stage) + R6's prep-fused wkv7/post.
// ---------------------------------------------------------------------------

#define BB 4
#define TT 2048
#define CC 2048
#define HH 32
#define NN 64
#define BT (BB*TT)                       // 8192
#define BTC ((size_t)BT*(size_t)CC)      // 16777216

__device__ float g_pool[23ull * 16777216ull];

#define SL_XR 0
#define SL_XW 1
#define SL_XK 2
#define SL_XV 3
#define SL_XA 4
#define SL_XG 5
#define SL_R  6
#define SL_K  7
#define SL_VL 8
#define SL_G  9
#define SL_WD 10
#define SL_A  11
#define SL_S  12
#define SL_Y  19
#define SL_ZS 20
#define SL_SMALL 21
#define SL_WB  22

// ===========================================================================
// helpers
// ===========================================================================
__device__ __forceinline__ uint32_t smem_u32(const void* p) {
    uint32_t a;
    asm("{ .reg .u64 t; cvta.to.shared.u64 t, %1; cvt.u32.u64 %0, t; }"
        : "=r"(a) : "l"(p));
    return a;
}
__device__ __forceinline__ void cpasync16(uint32_t dst, const void* src) {
    asm volatile("cp.async.cg.shared.global [%0], [%1], 16;" :: "r"(dst), "l"(src));
}
__device__ __forceinline__ void ldsm4(uint32_t* r, uint32_t addr) {
    asm volatile("ldmatrix.sync.aligned.m8n8.x4.shared.b16 {%0,%1,%2,%3}, [%4];"
        : "=r"(r[0]), "=r"(r[1]), "=r"(r[2]), "=r"(r[3]) : "r"(addr));
}
__device__ __forceinline__ void mma16816(float* d, const uint32_t* a, const uint32_t* b) {
    asm volatile(
        "mma.sync.aligned.m16n8k16.row.col.f32.bf16.bf16.f32 "
        "{%0,%1,%2,%3}, {%4,%5,%6,%7}, {%8,%9}, {%0,%1,%2,%3};"
        : "+f"(d[0]), "+f"(d[1]), "+f"(d[2]), "+f"(d[3])
        : "r"(a[0]), "r"(a[1]), "r"(a[2]), "r"(a[3]), "r"(b[0]), "r"(b[1]));
}
__device__ __forceinline__ uint32_t pack_bf2(float a, float b) {
    __nv_bfloat162 t = __floats2bfloat162_rn(a, b);
    return *reinterpret_cast<uint32_t*>(&t);
}

template<int EPI>
__device__ __forceinline__ float epi_apply(float v, float b) {
    if (EPI == 3) {
        return 1.f / (1.f + expf(-(v + b)));
    } else if (EPI == 4) {
        float z  = v + b;
        float sp = (z < -20.f) ? (-z) : log1pf(expf(-z));
        float w  = -sp - 0.5f;
        return expf(-expf(w));
    }
    return v;
}

// ===========================================================================
// Main tensor GEMM (R5 config): C[M,Ntot] = (Ah+Al)[M,K(lda)] @ (Bh+Bl)[Ntot,K]^T
// D = Ah*Bh + Ah*Bl + Al*Bh, fp32 accum. CTA 128x128x32, 4-stage cp.async,
// warp tile 64x32 (2x4 warps).
// ===========================================================================
#define PADK 40
#define TILE_B (128*PADK*2)              // 10240 bytes per operand tile
#define STG_B  (4*TILE_B)                // 40960
#define HSTAGES 4
#define HSMEM  (HSTAGES*STG_B)           // 163840

template<int EPI>
__global__ void __launch_bounds__(256, 1)
hgemm(const __nv_bfloat16* __restrict__ Ah, const __nv_bfloat16* __restrict__ Al,
      const __nv_bfloat16* __restrict__ Bh, const __nv_bfloat16* __restrict__ Bl,
      float* __restrict__ C, int K, int lda, int Ntot, const float* __restrict__ bias)
{
    extern __shared__ char sm[];
    const int tid  = threadIdx.x;
    const int lane = tid & 31;
    const int wid  = tid >> 5;
    const int m0 = blockIdx.y * 128;
    const int n0 = blockIdx.x * 128;
    const int mw = (wid >> 2) * 64;
    const int nw = (wid & 3) * 32;
    const uint32_t sbase = smem_u32(sm);
    const int KT = K >> 5;

    float acc[4][4][4];
#pragma unroll
    for (int mt = 0; mt < 4; mt++)
#pragma unroll
        for (int nt = 0; nt < 4; nt++)
#pragma unroll
            for (int q = 0; q < 4; q++) acc[mt][nt][q] = 0.f;

    auto issue = [&](int kt, int stage) {
        const int k0 = kt << 5;
        const uint32_t sdst = sbase + stage * STG_B;
#pragma unroll
        for (int u = 0; u < 8; u++) {
            int i  = tid + u * 256;
            int op = i >> 9;
            int r  = (i & 511) >> 2;
            int c  = i & 3;
            const __nv_bfloat16* src;
            if (op == 0)      src = Ah + (size_t)(m0 + r) * lda + k0 + c * 8;
            else if (op == 1) src = Al + (size_t)(m0 + r) * lda + k0 + c * 8;
            else if (op == 2) src = Bh + (size_t)(n0 + r) * K + k0 + c * 8;
            else              src = Bl + (size_t)(n0 + r) * K + k0 + c * 8;
            cpasync16(sdst + op * TILE_B + r * (PADK*2) + c * 16, src);
        }
    };

#pragma unroll
    for (int s = 0; s < HSTAGES - 1; s++) {
        if (s < KT) issue(s, s);
        asm volatile("cp.async.commit_group;" ::: "memory");
    }

    const int grp = lane >> 3;
    const int l7  = lane & 7;

    for (int kt = 0; kt < KT; kt++) {
        asm volatile("cp.async.wait_group 2;" ::: "memory");
        __syncthreads();

        const int st = kt % HSTAGES;
        const uint32_t sAh = sbase + st * STG_B;
        const uint32_t sAl = sAh + TILE_B;
        const uint32_t sBh = sAh + 2 * TILE_B;
        const uint32_t sBl = sAh + 3 * TILE_B;

#pragma unroll
        for (int kk = 0; kk < 2; kk++) {
            const int ko = kk * 16;
            uint32_t ahf[4][4], alf[4][4], bhf[4][2], blf[4][2];
#pragma unroll
            for (int mt = 0; mt < 4; mt++) {
                int row = mw + mt * 16 + ((grp & 1) << 3) + l7;
                int kof = ko + ((grp & 2) << 2);
                uint32_t a = row * (PADK*2) + kof * 2;
                ldsm4(ahf[mt], sAh + a);
                ldsm4(alf[mt], sAl + a);
            }
#pragma unroll
            for (int np = 0; np < 2; np++) {
                int row = nw + np * 16 + ((grp >> 1) << 3) + l7;
                int kof = ko + ((grp & 1) << 3);
                uint32_t a = row * (PADK*2) + kof * 2;
                uint32_t t[4];
                ldsm4(t, sBh + a);
                bhf[np*2][0]   = t[0]; bhf[np*2][1]   = t[1];
                bhf[np*2+1][0] = t[2]; bhf[np*2+1][1] = t[3];
                ldsm4(t, sBl + a);
                blf[np*2][0]   = t[0]; blf[np*2][1]   = t[1];
                blf[np*2+1][0] = t[2]; blf[np*2+1][1] = t[3];
            }
#pragma unroll
            for (int mt = 0; mt < 4; mt++)
#pragma unroll
                for (int nt = 0; nt < 4; nt++) {
                    mma16816(acc[mt][nt], ahf[mt], bhf[nt]);
                    mma16816(acc[mt][nt], ahf[mt], blf[nt]);
                    mma16816(acc[mt][nt], alf[mt], bhf[nt]);
                }
        }

        int nkt = kt + HSTAGES - 1;
        if (nkt < KT) issue(nkt, nkt % HSTAGES);
        asm volatile("cp.async.commit_group;" ::: "memory");
    }

    const int r0 = lane >> 2;
    const int c0 = (lane & 3) * 2;
#pragma unroll
    for (int mt = 0; mt < 4; mt++) {
#pragma unroll
        for (int nt = 0; nt < 4; nt++) {
            int row = m0 + mw + mt * 16 + r0;
            int col = n0 + nw + nt * 8 + c0;
            float b0 = 0.f, b1 = 0.f;
            if (EPI != 0) { b0 = bias[col]; b1 = bias[col + 1]; }
            float v0 = epi_apply<EPI>(acc[mt][nt][0], b0);
            float v1 = epi_apply<EPI>(acc[mt][nt][1], b1);
            float v2 = epi_apply<EPI>(acc[mt][nt][2], b0);
            float v3 = epi_apply<EPI>(acc[mt][nt][3], b1);
            *(float2*)(C + (size_t)row * Ntot + col)       = make_float2(v0, v1);
            *(float2*)(C + (size_t)(row + 8) * Ntot + col) = make_float2(v2, v3);
        }
    }
}

// ===========================================================================
// Stage-1 fused LoRA GEMM: 5 column segments of W1cat[320][2048].
// ===========================================================================
#define S1_ATILE (128*PADK*2)
#define S1_BTILE (64*PADK*2)
#define S1_STG   (2*S1_ATILE + 2*S1_BTILE)
#define S1_SMEM  (3*S1_STG)
#define HCATN 320

__global__ void __launch_bounds__(256, 1)
hgemm_s1(const __nv_bfloat16* __restrict__ xw_h, const __nv_bfloat16* __restrict__ xw_l,
         const __nv_bfloat16* __restrict__ xa_h, const __nv_bfloat16* __restrict__ xa_l,
         const __nv_bfloat16* __restrict__ xg_h, const __nv_bfloat16* __restrict__ xg_l,
         const __nv_bfloat16* __restrict__ xv_h, const __nv_bfloat16* __restrict__ xv_l,
         const __nv_bfloat16* __restrict__ W1h, const __nv_bfloat16* __restrict__ W1l,
         __nv_bfloat16* __restrict__ Hh, __nv_bfloat16* __restrict__ Hl)
{
    extern __shared__ char sm[];
    const int tid  = threadIdx.x;
    const int lane = tid & 31;
    const int wid  = tid >> 5;
    const int seg  = blockIdx.x;
    const int m0   = blockIdx.y * 128;
    const int n0w  = seg * 64;
    const uint32_t sbase = smem_u32(sm);

    const __nv_bfloat16* Ah;
    const __nv_bfloat16* Al;
    if (seg == 0)      { Ah = xw_h; Al = xw_l; }
    else if (seg == 1) { Ah = xa_h; Al = xa_l; }
    else if (seg <= 3) { Ah = xg_h; Al = xg_l; }
    else               { Ah = xv_h; Al = xv_l; }

    const int mw = (wid >> 1) * 32;
    const int nw = (wid & 1) * 32;

    float acc[2][4][4];
#pragma unroll
    for (int mt = 0; mt < 2; mt++)
#pragma unroll
        for (int nt = 0; nt < 4; nt++)
#pragma unroll
            for (int q = 0; q < 4; q++) acc[mt][nt][q] = 0.f;

    auto issue = [&](int kt, int stage) {
        const int k0 = kt << 5;
        const uint32_t sdst = sbase + stage * S1_STG;
#pragma unroll
        for (int u = 0; u < 6; u++) {
            int i = tid + u * 256;
            if (i < 1024) {
                int sp = i >> 9, r = (i >> 2) & 127, c = i & 3;
                const __nv_bfloat16* src = (sp ? Al : Ah) + (size_t)(m0 + r) * CC + k0 + c * 8;
                cpasync16(sdst + sp * S1_ATILE + r * (PADK*2) + c * 16, src);
            } else {
                int j = i - 1024;
                int sp = j >> 8, r = (j >> 2) & 63, c = j & 3;
                const __nv_bfloat16* src = (sp ? W1l : W1h) + (size_t)(n0w + r) * CC + k0 + c * 8;
                cpasync16(sdst + 2*S1_ATILE + sp * S1_BTILE + r * (PADK*2) + c * 16, src);
            }
        }
    };

#pragma unroll
    for (int s = 0; s < 2; s++) {
        issue(s, s);
        asm volatile("cp.async.commit_group;" ::: "memory");
    }

    const int grp = lane >> 3;
    const int l7  = lane & 7;
    const int KT = CC >> 5;

    for (int kt = 0; kt < KT; kt++) {
        asm volatile("cp.async.wait_group 1;" ::: "memory");
        __syncthreads();

        const int st = kt % 3;
        const uint32_t sAh = sbase + st * S1_STG;
        const uint32_t sAl = sAh + S1_ATILE;
        const uint32_t sBh = sAh + 2 * S1_ATILE;
        const uint32_t sBl = sBh + S1_BTILE;

#pragma unroll
        for (int kk = 0; kk < 2; kk++) {
            const int ko = kk * 16;
            uint32_t ahf[2][4], alf[2][4], bhf[4][2], blf[4][2];
#pragma unroll
            for (int mt = 0; mt < 2; mt++) {
                int row = mw + mt * 16 + ((grp & 1) << 3) + l7;
                int kof = ko + ((grp & 2) << 2);
                uint32_t a = row * (PADK*2) + kof * 2;
                ldsm4(ahf[mt], sAh + a);
                ldsm4(alf[mt], sAl + a);
            }
#pragma unroll
            for (int np = 0; np < 2; np++) {
                int row = nw + np * 16 + ((grp >> 1) << 3) + l7;
                int kof = ko + ((grp & 1) << 3);
                uint32_t a = row * (PADK*2) + kof * 2;
                uint32_t t[4];
                ldsm4(t, sBh + a);
                bhf[np*2][0]   = t[0]; bhf[np*2][1]   = t[1];
                bhf[np*2+1][0] = t[2]; bhf[np*2+1][1] = t[3];
                ldsm4(t, sBl + a);
                blf[np*2][0]   = t[0]; blf[np*2][1]   = t[1];
                blf[np*2+1][0] = t[2]; blf[np*2+1][1] = t[3];
            }
#pragma unroll
            for (int mt = 0; mt < 2; mt++)
#pragma unroll
                for (int nt = 0; nt < 4; nt++) {
                    mma16816(acc[mt][nt], ahf[mt], bhf[nt]);
                    mma16816(acc[mt][nt], ahf[mt], blf[nt]);
                    mma16816(acc[mt][nt], alf[mt], bhf[nt]);
                }
        }

        int nkt = kt + 2;
        if (nkt < KT) issue(nkt, nkt % 3);
        asm volatile("cp.async.commit_group;" ::: "memory");
    }

    const int r0 = lane >> 2;
    const int c0 = (lane & 3) * 2;
#pragma unroll
    for (int mt = 0; mt < 2; mt++) {
#pragma unroll
        for (int nt = 0; nt < 4; nt++) {
            float v[4];
#pragma unroll
            for (int q = 0; q < 4; q++) {
                float t = acc[mt][nt][q];
                if (seg == 0)              t = tanhf(t);
                else if (seg == 2 || seg == 3) t = 1.f / (1.f + expf(-t));
                v[q] = t;
            }
            int row = m0 + mw + mt * 16 + r0;
            int col = seg * 64 + nw + nt * 8 + c0;
            float h0 = __bfloat162float(__float2bfloat16(v[0]));
            float h1 = __bfloat162float(__float2bfloat16(v[1]));
            float h2 = __bfloat162float(__float2bfloat16(v[2]));
            float h3 = __bfloat162float(__float2bfloat16(v[3]));
            *(uint32_t*)&Hh[(size_t)row * HCATN + col]       = pack_bf2(v[0], v[1]);
            *(uint32_t*)&Hl[(size_t)row * HCATN + col]       = pack_bf2(v[0]-h0, v[1]-h1);
            *(uint32_t*)&Hh[(size_t)(row+8) * HCATN + col]   = pack_bf2(v[2], v[3]);
            *(uint32_t*)&Hl[(size_t)(row+8) * HCATN + col]   = pack_bf2(v[2]-h2, v[3]-h3);
        }
    }
}

// ===========================================================================
// Weight transpose + split: W[K][N] fp32 -> Th/Tl[N][K] bf16
// ===========================================================================
__global__ void transpose_split(const float* __restrict__ W,
                                __nv_bfloat16* __restrict__ Th,
                                __nv_bfloat16* __restrict__ Tl, int K, int N)
{
    __shared__ float tile[32][33];
    int bx = blockIdx.x * 32;
    int by = blockIdx.y * 32;
#pragma unroll
    for (int j = 0; j < 32; j += 8)
        tile[threadIdx.y + j][threadIdx.x] =
            W[(size_t)(by + threadIdx.y + j) * N + bx + threadIdx.x];
    __syncthreads();
#pragma unroll
    for (int j = 0; j < 32; j += 8) {
        float v = tile[threadIdx.x][threadIdx.y + j];
        int n = bx + threadIdx.y + j;
        int k = by + threadIdx.x;
        __nv_bfloat16 h = __float2bfloat16(v);
        Th[(size_t)n * K + k] = h;
        Tl[(size_t)n * K + k] = __float2bfloat16(v - __bfloat162float(h));
    }
}

// ---------------------------------------------------------------------------
// Token-shift mixing, fused bf16 hi/lo split output for all 6 streams.
// ---------------------------------------------------------------------------
__global__ void mix_split_kernel(const float* __restrict__ x,
    const float* __restrict__ mr, const float* __restrict__ mw,
    const float* __restrict__ mk, const float* __restrict__ mv,
    const float* __restrict__ ma, const float* __restrict__ mg,
    __nv_bfloat16* __restrict__ rh, __nv_bfloat16* __restrict__ rl,
    __nv_bfloat16* __restrict__ wh, __nv_bfloat16* __restrict__ wl,
    __nv_bfloat16* __restrict__ kh, __nv_bfloat16* __restrict__ kl,
    __nv_bfloat16* __restrict__ vh, __nv_bfloat16* __restrict__ vl,
    __nv_bfloat16* __restrict__ ah, __nv_bfloat16* __restrict__ al,
    __nv_bfloat16* __restrict__ gh, __nv_bfloat16* __restrict__ gl)
{
    size_t i = (size_t)blockIdx.x * blockDim.x + threadIdx.x;
    size_t n4 = BTC / 4;
    if (i >= n4) return;
    size_t e = i * 4;
    int c  = (int)(e % CC);
    int bt = (int)(e / CC);
    int t  = bt % TT;

    float4 xc = ((const float4*)x)[i];
    float4 xp = make_float4(0.f, 0.f, 0.f, 0.f);
    if (t > 0) xp = ((const float4*)x)[i - CC/4];
    float4 xx = make_float4(xp.x-xc.x, xp.y-xc.y, xp.z-xc.z, xp.w-xc.w);

    int c4 = c / 4;
#define DOMIX(MV, OH, OL) { \
        float4 m = ((const float4*)MV)[c4]; \
        float4 o = make_float4(xc.x + xx.x*m.x, xc.y + xx.y*m.y, \
                               xc.z + xx.z*m.z, xc.w + xx.w*m.w); \
        float h0 = __bfloat162float(__float2bfloat16(o.x)); \
        float h1 = __bfloat162float(__float2bfloat16(o.y)); \
        float h2 = __bfloat162float(__float2bfloat16(o.z)); \
        float h3 = __bfloat162float(__float2bfloat16(o.w)); \
        ((uint2*)OH)[i] = make_uint2(pack_bf2(o.x, o.y), pack_bf2(o.z, o.w)); \
        ((uint2*)OL)[i] = make_uint2(pack_bf2(o.x-h0, o.y-h1), pack_bf2(o.z-h2, o.w-h3)); }
    DOMIX(mr, rh, rl); DOMIX(mw, wh, wl); DOMIX(mk, kh, kl);
    DOMIX(mv, vh, vl); DOMIX(ma, ah, al); DOMIX(mg, gh, gl);
#undef DOMIX
}

// ---------------------------------------------------------------------------
__device__ __forceinline__ float warp_sum(float v) {
#pragma unroll
    for (int o = 16; o > 0; o >>= 1) v += __shfl_xor_sync(0xffffffffu, v, o);
    return v;
}

// ---------------------------------------------------------------------------
// WKV7 recurrence with fused prep. 256 threads/block, one block per (b,h).
// ---------------------------------------------------------------------------
__global__ void __launch_bounds__(256)
wkv7_kernel(const float* __restrict__ r_,  const float* __restrict__ wd_,
            const float* __restrict__ k_,  const float* __restrict__ a_,
            const float* __restrict__ vl_, const float* __restrict__ s_,
            const float* __restrict__ v0_,
            const float* __restrict__ misc_kkk, const float* __restrict__ misc_a,
            float* __restrict__ yT)
{
    __shared__ __align__(16) float sb[2*392];
    const int bh  = blockIdx.x;
    const int b   = bh >> 5, h = bh & 31;
    const int tid = threadIdx.x;
    const int tg  = tid >> 6;
    const int n   = tid & 63;
    const int row = tid >> 2;
    const int cg  = tid & 3;
    const int cb  = cg * 16;
    const size_t src0  = ((size_t)b * TT) * CC + (size_t)h * NN + n;
    const size_t ybase = (size_t)bh * TT * NN;

    const float* pA;
    const float* pB = nullptr;
    const float* pC = nullptr;
    float ma = 0.f, mkk = 0.f;
    if (tg == 0)      pA = r_  + src0;
    else if (tg == 1) pA = wd_ + src0;
    else if (tg == 2) { pA = k_ + src0; pB = a_ + src0;
                        mkk = misc_kkk[h*NN+n]; ma = misc_a[h*NN+n]; }
    else              { pA = vl_ + src0; pB = s_ + src0; pC = v0_ + src0; }

    float st[16];
#pragma unroll
    for (int j = 0; j < 16; j++) st[j] = 0.f;

    {
        float va = pA[0];
        if (tg == 0)      sb[0*64+n] = va;
        else if (tg == 1) sb[1*64+n] = va;
        else if (tg == 2) {
            float vb = pB[0];
            float kk = va * mkk;
            sb[2*64+n] = va * fmaf(vb - 1.f, ma, 1.f);
            sb[4*64+n] = -kk;
            sb[5*64+n] = kk * vb;
            float wsum = warp_sum(kk*kk);
            if ((tid & 31) == 0) sb[384 + ((tid >> 5) & 1)] = wsum;
        } else {
            float vb = pB[0], vc = pC[0];
            sb[3*64+n] = va + (vc - va) * vb;
        }
    }
    __syncthreads();

    int cur = 0;
    for (int t = 0; t < TT; t++) {
        float fa = 0.f, fb = 0.f, fc = 0.f;
        if (t + 1 < TT) {
            size_t o = (size_t)(t + 1) * CC;
            fa = pA[o];
            if (tg >= 2) fb = pB[o];
            if (tg == 3) fc = pC[o];
        }

        const float* base = &sb[cur * 392];
        float ssq  = base[384] + base[385];
        float invn = 1.f / fmaxf(sqrtf(ssq), 1e-12f);
        float f2   = invn * invn;

        const float4* r4p = (const float4*)(base + 0*64 + cb);
        const float4* w4p = (const float4*)(base + 1*64 + cb);
        const float4* k4p = (const float4*)(base + 2*64 + cb);
        const float4* a4p = (const float4*)(base + 4*64 + cb);
        const float4* b4p = (const float4*)(base + 5*64 + cb);
        const float vi = base[3*64 + row];

        float c0=0.f, c1=0.f, c2=0.f, c3=0.f;
#pragma unroll
        for (int q = 0; q < 4; q++) {
            float4 a4 = a4p[q];
            c0 = fmaf(st[q*4+0], a4.x, c0);
            c1 = fmaf(st[q*4+1], a4.y, c1);
            c2 = fmaf(st[q*4+2], a4.z, c2);
            c3 = fmaf(st[q*4+3], a4.w, c3);
        }
        float sai = (c0 + c1) + (c2 + c3);
        sai += __shfl_xor_sync(0xffffffffu, sai, 1);
        sai += __shfl_xor_sync(0xffffffffu, sai, 2);
        sai *= f2;

        float y0=0.f, y1=0.f, y2=0.f, y3=0.f;
#pragma unroll
        for (int q = 0; q < 4; q++) {
            float4 w4 = w4p[q], b4 = b4p[q], k4 = k4p[q], r4 = r4p[q];
            float t0 = fmaf(sai, b4.x, fmaf(vi, k4.x, st[q*4+0]*w4.x));
            float t1 = fmaf(sai, b4.y, fmaf(vi, k4.y, st[q*4+1]*w4.y));
            float t2 = fmaf(sai, b4.z, fmaf(vi, k4.z, st[q*4+2]*w4.z));
            float t3 = fmaf(sai, b4.w, fmaf(vi, k4.w, st[q*4+3]*w4.w));
            st[q*4+0] = t0; st[q*4+1] = t1; st[q*4+2] = t2; st[q*4+3] = t3;
            y0 = fmaf(t0, r4.x, y0);
            y1 = fmaf(t1, r4.y, y1);
            y2 = fmaf(t2, r4.z, y2);
            y3 = fmaf(t3, r4.w, y3);
        }
        float yp = (y0 + y1) + (y2 + y3);
        yp += __shfl_xor_sync(0xffffffffu, yp, 1);
        yp += __shfl_xor_sync(0xffffffffu, yp, 2);
        if (cg == 0) yT[ybase + (size_t)t * NN + row] = yp;

        int nxt = cur ^ 1;
        if (t + 1 < TT) {
            float* d = &sb[nxt * 392];
            if (tg == 0)      d[0*64+n] = fa;
            else if (tg == 1) d[1*64+n] = fa;
            else if (tg == 2) {
                float kk = fa * mkk;
                d[2*64+n] = fa * fmaf(fb - 1.f, ma, 1.f);
                d[4*64+n] = -kk;
                d[5*64+n] = kk * fb;
                float wsum = warp_sum(kk*kk);
                if ((tid & 31) == 0) d[384 + ((tid >> 5) & 1)] = wsum;
            } else {
                d[3*64+n] = fa + (fc - fa) * fb;
            }
        }
        __syncthreads();
        cur = nxt;
    }
}

// ---------------------------------------------------------------------------
// GroupNorm + bonus + gate (prep transforms recomputed inline).
// ---------------------------------------------------------------------------
__global__ void post_kernel(const float* __restrict__ yT,
                            const float* __restrict__ r_, const float* __restrict__ k_,
                            const float* __restrict__ a_, const float* __restrict__ vl_,
                            const float* __restrict__ s_, const float* __restrict__ v0_,
                            const float* __restrict__ g,  const float* __restrict__ faaaa,
                            const float* __restrict__ misc_a,
                            const float* __restrict__ lnw, const float* __restrict__ lnb,
                            __nv_bfloat16* __restrict__ zh, __nv_bfloat16* __restrict__ zl)
{
    int gw   = (blockIdx.x * blockDim.x + threadIdx.x) >> 5;
    int lane = threadIdx.x & 31;
    if (gw >= BT * HH) return;
    int h  = gw % HH;
    int bt = gw / HH;
    int b  = bt / TT, t = bt % TT;

    size_t src = (size_t)bt * CC + (size_t)h * NN;
    size_t dst = (((size_t)(b*HH + h)) * TT + t) * NN;
    int n0 = lane, n1 = lane + 32;
    int c0 = h*NN + n0, c1 = h*NN + n1;

    float y0 = yT[dst+n0], y1 = yT[dst+n1];
    float sum = warp_sum(y0 + y1);
    float sq  = warp_sum(y0*y0 + y1*y1);
    float mu  = sum * (1.f/64.f);
    float var = sq * (1.f/64.f) - mu*mu;
    float rs  = rsqrtf(var + 6.4e-4f);

    float k0 = k_[src+n0], k1 = k_[src+n1];
    float a0 = a_[src+n0], a1 = a_[src+n1];
    float fk0 = k0 * fmaf(a0 - 1.f, misc_a[c0], 1.f);
    float fk1 = k1 * fmaf(a1 - 1.f, misc_a[c1], 1.f);
    float rk = r_[src+n0]*fk0*faaaa[c0] + r_[src+n1]*fk1*faaaa[c1];
    float srk = warp_sum(rk);

    float vv0 = vl_[src+n0], vv1 = vl_[src+n1];
    float fv0 = vv0 + (v0_[src+n0] - vv0) * s_[src+n0];
    float fv1 = vv1 + (v0_[src+n1] - vv1) * s_[src+n1];

    float z0 = ((y0 - mu)*rs*lnw[c0] + lnb[c0] + srk*fv0) * g[src+n0];
    float z1 = ((y1 - mu)*rs*lnw[c1] + lnb[c1] + srk*fv1) * g[src+n1];
    __nv_bfloat16 h0 = __float2bfloat16(z0);
    __nv_bfloat16 h1 = __float2bfloat16(z1);
    zh[src+n0] = h0; zh[src+n1] = h1;
    zl[src+n0] = __float2bfloat16(z0 - __bfloat162float(h0));
    zl[src+n1] = __float2bfloat16(z1 - __bfloat162float(h1));
}

__global__ void copy4_kernel(const float* __restrict__ src, float* __restrict__ dst,
                             size_t n4)
{
    size_t i = (size_t)blockIdx.x * blockDim.x + threadIdx.x;
    if (i < n4) ((float4*)dst)[i] = ((const float4*)src)[i];
}

// ---------------------------------------------------------------------------
// launch
// ---------------------------------------------------------------------------
extern "C" void kernel_launch(void* const* d_in, const int* in_sizes, int n_in,
                              void* d_out, int out_size)
{
    const float* x         = (const float*)d_in[0];
    const float* v0        = (const float*)d_in[1];
    const float* maa_r     = (const float*)d_in[2];
    const float* maa_w     = (const float*)d_in[3];
    const float* maa_k     = (const float*)d_in[4];
    const float* maa_v     = (const float*)d_in[5];
    const float* maa_a     = (const float*)d_in[6];
    const float* maa_g     = (const float*)d_in[7];
    const float* time_decay= (const float*)d_in[8];
    const float* faaaa     = (const float*)d_in[9];
    const float* time_aaaaa= (const float*)d_in[10];
    const float* td_w1     = (const float*)d_in[11];
    const float* td_w2     = (const float*)d_in[12];
    const float* aaa_w1    = (const float*)d_in[13];
    const float* aaa_w2    = (const float*)d_in[14];
    const float* gate_w1   = (const float*)d_in[15];
    const float* gate_w2   = (const float*)d_in[16];
    const float* mv_w1     = (const float*)d_in[17];
    const float* mv_w2     = (const float*)d_in[18];
    const float* misc_v    = (const float*)d_in[19];
    const float* misc_kkk  = (const float*)d_in[20];
    const float* misc_a    = (const float*)d_in[21];
    const float* Wr        = (const float*)d_in[22];
    const float* Wk        = (const float*)d_in[23];
    const float* Wv        = (const float*)d_in[24];
    const float* Wo        = (const float*)d_in[25];
    const float* ln_w      = (const float*)d_in[26];
    const float* ln_b      = (const float*)d_in[27];

    float* pool = nullptr;
    cudaGetSymbolAddress((void**)&pool, g_pool);

    __nv_bfloat16* xr_h = (__nv_bfloat16*)(pool + (size_t)SL_XR * BTC);
    __nv_bfloat16* xr_l = xr_h + BTC;
    __nv_bfloat16* xw_h = (__nv_bfloat16*)(pool + (size_t)SL_XW * BTC);
    __nv_bfloat16* xw_l = xw_h + BTC;
    __nv_bfloat16* xk_h = (__nv_bfloat16*)(pool + (size_t)SL_XK * BTC);
    __nv_bfloat16* xk_l = xk_h + BTC;
    __nv_bfloat16* xv_h = (__nv_bfloat16*)(pool + (size_t)SL_XV * BTC);
    __nv_bfloat16* xv_l = xv_h + BTC;
    __nv_bfloat16* xa_h = (__nv_bfloat16*)(pool + (size_t)SL_XA * BTC);
    __nv_bfloat16* xa_l = xa_h + BTC;
    __nv_bfloat16* xg_h = (__nv_bfloat16*)(pool + (size_t)SL_XG * BTC);
    __nv_bfloat16* xg_l = xg_h + BTC;

    float* r_ = pool + (size_t)SL_R  * BTC;
    float* k_ = pool + (size_t)SL_K  * BTC;
    float* vl = pool + (size_t)SL_VL * BTC;
    float* g_ = pool + (size_t)SL_G  * BTC;
    float* wd = pool + (size_t)SL_WD * BTC;
    float* a_ = pool + (size_t)SL_A  * BTC;
    float* s_ = pool + (size_t)SL_S  * BTC;
    float* yT = pool + (size_t)SL_Y  * BTC;
    __nv_bfloat16* z_h = (__nv_bfloat16*)(pool + (size_t)SL_ZS * BTC);
    __nv_bfloat16* z_l = z_h + BTC;

    __nv_bfloat16* sb16 = (__nv_bfloat16*)(pool + (size_t)SL_SMALL * BTC);
    __nv_bfloat16* hcat_h = sb16;
    __nv_bfloat16* hcat_l = hcat_h + (size_t)BT * HCATN;
    __nv_bfloat16* W1h    = hcat_l + (size_t)BT * HCATN;
    __nv_bfloat16* W1l    = W1h + (size_t)HCATN * CC;
    __nv_bfloat16* tdw_h  = W1l + (size_t)HCATN * CC;
    __nv_bfloat16* tdw_l  = tdw_h  + (size_t)CC * 64;
    __nv_bfloat16* aaaw_h = tdw_l  + (size_t)CC * 64;
    __nv_bfloat16* aaaw_l = aaaw_h + (size_t)CC * 64;
    __nv_bfloat16* gatew_h= aaaw_l + (size_t)CC * 64;
    __nv_bfloat16* gatew_l= gatew_h+ (size_t)CC * 128;
    __nv_bfloat16* mvw_h  = gatew_l+ (size_t)CC * 128;
    __nv_bfloat16* mvw_l  = mvw_h  + (size_t)CC * 32;

    __nv_bfloat16* wb = (__nv_bfloat16*)(pool + (size_t)SL_WB * BTC);
    const size_t WSZ = (size_t)CC * CC;
    __nv_bfloat16* Wr_h = wb;            __nv_bfloat16* Wr_l = wb + WSZ;
    __nv_bfloat16* Wk_h = wb + 2*WSZ;    __nv_bfloat16* Wk_l = wb + 3*WSZ;
    __nv_bfloat16* Wv_h = wb + 4*WSZ;    __nv_bfloat16* Wv_l = wb + 5*WSZ;
    __nv_bfloat16* Wo_h = wb + 6*WSZ;    __nv_bfloat16* Wo_l = wb + 7*WSZ;

    cudaFuncSetAttribute(hgemm<0>, cudaFuncAttributeMaxDynamicSharedMemorySize, HSMEM);
    cudaFuncSetAttribute(hgemm<3>, cudaFuncAttributeMaxDynamicSharedMemorySize, HSMEM);
    cudaFuncSetAttribute(hgemm<4>, cudaFuncAttributeMaxDynamicSharedMemorySize, HSMEM);
    cudaFuncSetAttribute(hgemm_s1, cudaFuncAttributeMaxDynamicSharedMemorySize, S1_SMEM);

    dim3 tb(32, 8);
    dim3 gBig(CC/128, BT/128);          // (16, 64)
    size_t n4 = BTC / 4;

    // weight transposes
    transpose_split<<<dim3(CC/32, CC/32), tb>>>(Wr, Wr_h, Wr_l, CC, CC);
    transpose_split<<<dim3(CC/32, CC/32), tb>>>(Wk, Wk_h, Wk_l, CC, CC);
    transpose_split<<<dim3(CC/32, CC/32), tb>>>(Wv, Wv_h, Wv_l, CC, CC);
    transpose_split<<<dim3(CC/32, CC/32), tb>>>(Wo, Wo_h, Wo_l, CC, CC);
    transpose_split<<<dim3(64/32,  CC/32), tb>>>(td_w1,   W1h,                 W1l,                 CC, 64);
    transpose_split<<<dim3(64/32,  CC/32), tb>>>(aaa_w1,  W1h + (size_t)64*CC, W1l + (size_t)64*CC, CC, 64);
    transpose_split<<<dim3(128/32, CC/32), tb>>>(gate_w1, W1h + (size_t)128*CC,W1l + (size_t)128*CC,CC, 128);
    transpose_split<<<dim3(32/32,  CC/32), tb>>>(mv_w1,   W1h + (size_t)256*CC,W1l + (size_t)256*CC,CC, 32);
    transpose_split<<<dim3(CC/32, 64/32),  tb>>>(td_w2,  tdw_h,  tdw_l,  64,  CC);
    transpose_split<<<dim3(CC/32, 64/32),  tb>>>(aaa_w2, aaaw_h, aaaw_l, 64,  CC);
    transpose_split<<<dim3(CC/32, 128/32), tb>>>(gate_w2,gatew_h,gatew_l,128, CC);
    transpose_split<<<dim3(CC/32, 32/32),  tb>>>(mv_w2,  mvw_h,  mvw_l,  32,  CC);

    // token-shift mixing + split
    mix_split_kernel<<<(unsigned)((n4 + 255) / 256), 256>>>(
        x, maa_r, maa_w, maa_k, maa_v, maa_a, maa_g,
        xr_h, xr_l, xw_h, xw_l, xk_h, xk_l, xv_h, xv_l, xa_h, xa_l, xg_h, xg_l);

    // big projections
    hgemm<0><<<gBig, 256, HSMEM>>>(xr_h, xr_l, Wr_h, Wr_l, r_, CC, CC, CC, nullptr);
    hgemm<0><<<gBig, 256, HSMEM>>>(xk_h, xk_l, Wk_h, Wk_l, k_, CC, CC, CC, nullptr);
    hgemm<0><<<gBig, 256, HSMEM>>>(xv_h, xv_l, Wv_h, Wv_l, vl, CC, CC, CC, nullptr);

    // stage-1 fused LoRA GEMM
    hgemm_s1<<<dim3(5, BT/128), 256, S1_SMEM>>>(
        xw_h, xw_l, xa_h, xa_l, xg_h, xg_l, xv_h, xv_l, W1h, W1l, hcat_h, hcat_l);

    // stage-2 GEMMs (fused epilogues)
    hgemm<4><<<gBig, 256, HSMEM>>>(hcat_h,     hcat_l,     tdw_h,  tdw_l,  wd, 64,  HCATN, CC, time_decay);
    hgemm<3><<<gBig, 256, HSMEM>>>(hcat_h+64,  hcat_l+64,  aaaw_h, aaaw_l, a_, 64,  HCATN, CC, time_aaaaa);
    hgemm<0><<<gBig, 256, HSMEM>>>(hcat_h+128, hcat_l+128, gatew_h,gatew_l,g_, 128, HCATN, CC, nullptr);
    hgemm<3><<<gBig, 256, HSMEM>>>(hcat_h+256, hcat_l+256, mvw_h,  mvw_l,  s_, 32,  HCATN, CC, misc_v);

    // WKV7 recurrence (prep fused into staging)
    wkv7_kernel<<<BB*HH, 256>>>(r_, wd, k_, a_, vl, s_, v0, misc_kkk, misc_a, yT);

    // groupnorm + bonus + gate -> z split
    post_kernel<<<(BT*HH)/8, 256>>>(yT, r_, k_, a_, vl, s_, v0, g_, faaaa,
                                    misc_a, ln_w, ln_b, z_h, z_l);

    // output projection directly into d_out
    hgemm<0><<<gBig, 256, HSMEM>>>(z_h, z_l, Wo_h, Wo_l, (float*)d_out, CC, CC, CC, nullptr);

    // second output: v0 passthrough
    if ((size_t)out_size >= 2 * BTC) {
        copy4_kernel<<<(unsigned)((n4 + 255) / 256), 256>>>(
            v0, (float*)d_out + BTC, n4);
    }
}